// round 15
// baseline (speedup 1.0000x reference)
#include <cuda_runtime.h>
#include <cuda_fp16.h>
#include <math.h>
#include <stdint.h>

#define BB 16
#define SS 2048
#define DD 1024
#define NN 16
#define M_TOT (BB*SS)   // 32768 tokens

// ---------------- scratch (__device__ globals) ------------------------------
__device__ __align__(256) float g_a[M_TOT*NN];
__device__ __align__(256) float g_b[M_TOT*NN];
__device__ __align__(256) __half g_hhi[M_TOT*NN];
__device__ __align__(256) __half g_hlo[M_TOT*NN];
__device__ __align__(256) __half g_xhi[(size_t)M_TOT*DD];
__device__ __align__(256) __half g_whi[2048*DD];
__device__ __align__(256) __half g_wabhi[32*DD];
__device__ __align__(256) __half g_wablo[32*DD];
__device__ __align__(256) __half g_wchi[DD*NN];
__device__ __align__(256) __half g_wclo[DD*NN];

// ---------------- PTX helpers ----------------------------------------------
__device__ __forceinline__ uint32_t smem_u32(const void* p) {
    uint32_t a;
    asm("{ .reg .u64 t; cvta.to.shared.u64 t, %1; cvt.u32.u64 %0, t; }" : "=r"(a) : "l"(p));
    return a;
}
__device__ __forceinline__ void cp16(uint32_t dst, const void* src) {
    asm volatile("cp.async.cg.shared.global [%0], [%1], 16;" :: "r"(dst), "l"(src) : "memory");
}
#define CP_COMMIT() asm volatile("cp.async.commit_group;" ::: "memory")
#define CP_WAIT1()  asm volatile("cp.async.wait_group 1;" ::: "memory")
#define CP_WAIT0()  asm volatile("cp.async.wait_group 0;" ::: "memory")

__device__ __forceinline__ void ldsm4(uint32_t* r, uint32_t addr) {
    asm volatile("ldmatrix.sync.aligned.m8n8.x4.shared.b16 {%0,%1,%2,%3}, [%4];"
                 : "=r"(r[0]), "=r"(r[1]), "=r"(r[2]), "=r"(r[3]) : "r"(addr));
}
__device__ __forceinline__ void mma16816(float* d, const uint32_t* a, const uint32_t* b) {
    asm volatile("mma.sync.aligned.m16n8k16.row.col.f32.f16.f16.f32 "
                 "{%0,%1,%2,%3}, {%4,%5,%6,%7}, {%8,%9}, {%0,%1,%2,%3};"
                 : "+f"(d[0]), "+f"(d[1]), "+f"(d[2]), "+f"(d[3])
                 : "r"(a[0]), "r"(a[1]), "r"(a[2]), "r"(a[3]), "r"(b[0]), "r"(b[1]));
}

// ---------------------------------------------------------------------------
// wab: WA/WB hi/lo (32x1024) and WC hi/lo (1024x16)  (prep dependency)
// ---------------------------------------------------------------------------
__global__ __launch_bounds__(256) void wab_kernel(const float* __restrict__ WA,
                                                  const float* __restrict__ WB,
                                                  const float* __restrict__ WC)
{
    int id = blockIdx.x * 256 + threadIdx.x;      // 192 blocks -> 49152
    float v;
    if (id < 32768) {
        int r = id >> 10, c = id & 1023;
        v = (r < 16) ? WA[(size_t)r * DD + c] : WB[(size_t)(r - 16) * DD + c];
        __half h = __float2half_rn(v);
        g_wabhi[id] = h;
        g_wablo[id] = __float2half_rn(v - __half2float(h));
    } else {
        int i2 = id - 32768;
        v = WC[i2];
        __half h = __float2half_rn(v);
        g_wchi[i2] = h;
        g_wclo[i2] = __float2half_rn(v - __half2float(h));
    }
}

// ---------------------------------------------------------------------------
// wmain: W pair-interleave -> g_whi (only main_kernel consumes; side stream)
// ---------------------------------------------------------------------------
__global__ __launch_bounds__(256) void wmain_kernel(const float* __restrict__ Wg,
                                                    const float* __restrict__ WD)
{
    int idx = blockIdx.x * 256 + threadIdx.x;     // 2048 rows * 256 float4
    int r  = idx >> 8;
    int c4 = idx & 255;
    int j = r >> 8, q = r & 255;
    int p = q >> 4, s = q & 15;
    int e = j*128 + p*8 + (s & 7);
    const float* src = (s < 8) ? (Wg + (size_t)e * DD) : (WD + (size_t)e * DD);
    float4 v = ((const float4*)src)[c4];
    __half2 hA = __floats2half2_rn(v.x, v.y);
    __half2 hB = __floats2half2_rn(v.z, v.w);
    uint2 hp;
    hp.x = *(uint32_t*)&hA; hp.y = *(uint32_t*)&hB;
    *(uint2*)(g_whi + (size_t)r * DD + c4 * 4) = hp;
}

// ---------------------------------------------------------------------------
// prep: W resident in smem, double-buffered x staging, overlapped cp.async.
// a=tanh(x@WA^T), b=x@WB^T via 3-term fp16 HMMA; writes g_xhi.
// ---------------------------------------------------------------------------
#define PXF0 0
#define PXF1 32768
#define PXH  65536
#define PXL  81920
#define PWH  98304
#define PWL  163840
#define PREP_SMEM 229376
#define PXFS 256

__global__ __launch_bounds__(256) void prep_kernel(const float* __restrict__ x)
{
    extern __shared__ char smem[];
    uint32_t sb = smem_u32(smem);
    const int tid  = threadIdx.x;
    const int lane = tid & 31;
    const int wid  = tid >> 5;
    const int m0   = blockIdx.x * 128;
    const uint32_t lh = lane & 7;

    // W resident: 16 chunk-tiles (32 rows x 64 cols each), hi + lo
    #pragma unroll
    for (int i = 0; i < 16; i++) {
        int u = tid + i * 256;            // 0..4095
        int c = u >> 8, v = u & 255, row = v >> 3, c16 = v & 7;
        uint32_t off = (uint32_t)(c * 4096 + row * 128 + ((c16 ^ (row & 7)) << 4));
        const size_t gs = (size_t)row * DD + c * 64 + c16 * 8;
        cp16(sb + PWH + off, g_wabhi + gs);
        cp16(sb + PWL + off, g_wablo + gs);
    }
    CP_COMMIT();
    // x chunk 0
    #pragma unroll
    for (int i = 0; i < 8; i++) {
        int u = tid + i * 256;
        int row = u >> 4, q = u & 15;
        cp16(sb + PXF0 + row * PXFS + q * 16, x + (size_t)(m0 + row) * DD + q * 4);
    }
    CP_COMMIT();

    float acc[4][4] = {};

    for (int kc = 0; kc < 16; kc++) {
        CP_WAIT0();                        // x chunk kc (+ W at kc=0)
        if (kc < 15) {
            uint32_t nbuf = ((kc + 1) & 1) ? PXF1 : PXF0;
            #pragma unroll
            for (int i = 0; i < 8; i++) {
                int u = tid + i * 256;
                int row = u >> 4, q = u & 15;
                cp16(sb + nbuf + row * PXFS + q * 16,
                     x + (size_t)(m0 + row) * DD + (kc + 1) * 64 + q * 4);
            }
            CP_COMMIT();
        }
        uint32_t pxf = (kc & 1) ? PXF1 : PXF0;
        #pragma unroll
        for (int i = 0; i < 8; i++) {
            int u = tid + i * 256;
            int row = u >> 4, q = u & 15;
            float4 v = *(const float4*)(smem + pxf + row * PXFS + q * 16);
            __half hx = __float2half_rn(v.x), hy = __float2half_rn(v.y);
            __half hz = __float2half_rn(v.z), hw = __float2half_rn(v.w);
            __half2 hA = __halves2half2(hx, hy), hB = __halves2half2(hz, hw);
            __half2 lA = __floats2half2_rn(v.x - __half2float(hx), v.y - __half2float(hy));
            __half2 lB = __floats2half2_rn(v.z - __half2float(hz), v.w - __half2float(hw));
            uint2 hp, lp;
            hp.x = *(uint32_t*)&hA; hp.y = *(uint32_t*)&hB;
            lp.x = *(uint32_t*)&lA; lp.y = *(uint32_t*)&lB;
            int c16 = q >> 1;
            uint32_t soff = row * 128 + (((uint32_t)c16 ^ (row & 7)) << 4) + (q & 1) * 8;
            *(uint2*)(smem + PXH + soff) = hp;
            *(uint2*)(smem + PXL + soff) = lp;
            *(uint2*)(g_xhi + (size_t)(m0 + row) * DD + kc * 64 + q * 4) = hp;
        }
        __syncthreads();

        const uint32_t aBase = (uint32_t)((wid * 16 + (lane & 15)) * 128);
        const uint32_t bRow  = (uint32_t)(((lane >> 4) << 3) + lh);
        const uint32_t wchk  = (uint32_t)(kc * 4096);
        #pragma unroll
        for (int kk = 0; kk < 4; kk++) {
            uint32_t aSw = (((uint32_t)(kk*2) + (lane >> 4)) ^ lh) << 4;
            uint32_t bSw = (((uint32_t)(kk*2) + ((lane >> 3) & 1)) ^ lh) << 4;
            uint32_t ah[4], al[4], bh[8], bl[8];
            ldsm4(ah, sb + PXH + aBase + aSw);
            ldsm4(al, sb + PXL + aBase + aSw);
            ldsm4(&bh[0], sb + PWH + wchk + bRow * 128 + bSw);
            ldsm4(&bh[4], sb + PWH + wchk + (bRow + 16) * 128 + bSw);
            ldsm4(&bl[0], sb + PWL + wchk + bRow * 128 + bSw);
            ldsm4(&bl[4], sb + PWL + wchk + (bRow + 16) * 128 + bSw);
            #pragma unroll
            for (int ni = 0; ni < 4; ni++) {
                mma16816(acc[ni], ah, &bh[ni*2]);
                mma16816(acc[ni], ah, &bl[ni*2]);
                mma16816(acc[ni], al, &bh[ni*2]);
            }
        }
        __syncthreads();
    }

    #pragma unroll
    for (int ni = 0; ni < 4; ni++) {
        #pragma unroll
        for (int fr = 0; fr < 4; fr++) {
            int row = m0 + wid*16 + (lane >> 2) + (fr >> 1) * 8;
            int col = ni*8 + (lane & 3) * 2 + (fr & 1);
            float v = acc[ni][fr];
            if (col < 16) g_a[(size_t)row * NN + col]        = tanhf(v);
            else          g_b[(size_t)row * NN + (col - 16)] = v;
        }
    }
}

// ---------------------------------------------------------------------------
// Fused scan: grid 16, 512 thr = 16 chains x 32 chunks of 64 steps.
// ---------------------------------------------------------------------------
__global__ __launch_bounds__(512) void scanf_kernel()
{
    __shared__ float sA[16*33];
    __shared__ float sB[16*33];
    const int tid = threadIdx.x;
    const int n  = tid & 15;
    const int ch = tid >> 4;          // 0..31
    const int b  = blockIdx.x;
    const size_t base = ((size_t)b * SS + ch * 64) * NN + n;

    float A = 1.0f, h = 0.0f;
    #pragma unroll 4
    for (int i = 0; i < 64; i++) {
        float av = g_a[base + (size_t)i * NN];
        float bv = g_b[base + (size_t)i * NN];
        A *= av;
        h = fmaf(av, h, bv);
    }
    sA[n*33 + ch] = A;
    sB[n*33 + ch] = h;
    __syncthreads();

    if (tid < 16) {
        float carry = 0.0f;
        #pragma unroll
        for (int c = 0; c < 32; c++) {
            float a2 = sA[tid*33 + c];
            float b2 = sB[tid*33 + c];
            sB[tid*33 + c] = carry;
            carry = fmaf(a2, carry, b2);
        }
    }
    __syncthreads();

    h = sB[n*33 + ch];
    #pragma unroll 4
    for (int i = 0; i < 64; i++) {
        size_t idx = base + (size_t)i * NN;
        h = fmaf(g_a[idx], h, g_b[idx]);
        __half hh = __float2half_rn(h);
        g_hhi[idx] = hh;
        g_hlo[idx] = __float2half_rn(h - __half2float(hh));
    }
}

// ---------------------------------------------------------------------------
// Main: CTA 128x128, 256 thr, grid (16, 256), 2 CTAs/SM. Single-term fp16,
// 3-stage ring (prologue {0,1}; wait1 -> sync -> prefetch c+2 -> compute c),
// register epilogue (y-GEMM + gating).
// ---------------------------------------------------------------------------
#define STG      32768               // A 16K | W 16K
#define SW       16384
#define HT_OFF   (3*STG)             // 98304: hhi(4K)|hlo(4K)|wchi(2K)|wclo(2K)
#define SMEM_BYTES (HT_OFF + 12288)  // 110592 -> 2 CTAs/SM
#define NCH 16

__device__ __forceinline__ void load_chunk(uint32_t sb, int c, int m0, int jw, int tid)
{
    int kc = c * 64;
    uint32_t buf = sb + (uint32_t)(c % 3) * STG;
    #pragma unroll
    for (int i = 0; i < 8; i++) {
        int u = tid + i * 256;        // 2048 cp16
        if (u < 1024) {               // A: 128 rows x 8 c16
            int row = u >> 3, c16 = u & 7;
            cp16(buf + row * 128 + ((c16 ^ (row & 7)) << 4),
                 g_xhi + (size_t)(m0 + row) * DD + kc + c16 * 8);
        } else {                      // W: 128 rows x 8 c16
            int v = u - 1024;
            int row = v >> 3, c16 = v & 7;
            cp16(buf + SW + row * 128 + ((c16 ^ (row & 7)) << 4),
                 g_whi + (size_t)(jw + row) * DD + kc + c16 * 8);
        }
    }
    CP_COMMIT();
}

__global__ __launch_bounds__(256, 2) void main_kernel(const float* __restrict__ bD,
                                                      const float* __restrict__ bg,
                                                      float* __restrict__ out)
{
    extern __shared__ char smem[];
    uint32_t sb = smem_u32(smem);
    const int tid    = threadIdx.x;
    const int lane   = tid & 31;
    const int wid    = tid >> 5;
    const int warp_m = wid & 1;       // 2 m-groups of 64 rows
    const int warp_n = wid >> 1;      // 4 n-groups of 32 cols
    const int j  = blockIdx.x;        // 0..15
    const int m0 = blockIdx.y * 128;
    const int jw = j * 128;
    const uint32_t lh = lane & 7;

    // HT tiles: hhi|hlo (128x16) + wchi|wclo (64x16) -> 768 cp16
    #pragma unroll
    for (int i = 0; i < 3; i++) {
        int u = tid + i * 256;            // 0..767
        const __half* src;
        uint32_t dst;
        if (u < 512) {                    // hhi / hlo
            int region = u >> 8, v = u & 255;
            int row = v >> 1, c16 = v & 1;
            src = (region == 0 ? g_hhi : g_hlo) + (size_t)(m0 + row) * NN + c16 * 8;
            dst = sb + HT_OFF + region * 4096 + row * 32 + c16 * 16;
        } else {                          // wchi / wclo
            int v = u - 512;
            int region = v >> 7, w = v & 127;
            int row = w >> 1, c16 = w & 1;
            src = (region == 0 ? g_wchi : g_wclo) + (size_t)(j*64 + row) * NN + c16 * 8;
            dst = sb + HT_OFF + 8192 + region * 2048 + row * 32 + c16 * 16;
        }
        cp16(dst, src);
    }
    load_chunk(sb, 0, m0, jw, tid);   // group 0 (includes HT)
    load_chunk(sb, 1, m0, jw, tid);   // group 1

    float d[4][4][4] = {};

    const uint32_t aBase = (uint32_t)((warp_m*64 + (lane & 15)) * 128);
    const uint32_t aHalf = (uint32_t)(lane >> 4);
    const uint32_t bBase = (uint32_t)(SW + (warp_n*32 + ((lane >> 4) << 3) + lh) * 128);
    const uint32_t bHalf = (uint32_t)((lane >> 3) & 1);

    for (int c = 0; c < NCH; c++) {
        if (c + 1 == NCH) CP_WAIT0(); else CP_WAIT1();
        __syncthreads();
        if (c + 2 < NCH) load_chunk(sb, c + 2, m0, jw, tid);

        uint32_t buf = sb + (uint32_t)(c % 3) * STG;
        #pragma unroll
        for (int kk = 0; kk < 4; kk++) {
            uint32_t aSw = (((uint32_t)(kk*2) + aHalf) ^ lh) << 4;
            uint32_t bSw = (((uint32_t)(kk*2) + bHalf) ^ lh) << 4;
            uint32_t b[8], a[4][4];
            ldsm4(&b[0], buf + bBase + bSw);
            ldsm4(&b[4], buf + bBase + 2048 + bSw);
            #pragma unroll
            for (int mi = 0; mi < 4; mi++)
                ldsm4(a[mi], buf + aBase + mi * 2048 + aSw);
            #pragma unroll
            for (int mi = 0; mi < 4; mi++)
                #pragma unroll
                for (int ni = 0; ni < 4; ni++)
                    mma16816(d[mi][ni], a[mi], &b[ni*2]);
        }
    }

    // ---- register epilogue: y = hs@WC^T (3-term fp16), then gating ----
    uint32_t bh[4], bl[4];
    const uint32_t bO = sb + HT_OFF + 8192 +
        (uint32_t)((warp_n*16 + ((lane >> 4) << 3) + lh) * 32 + ((lane >> 3) & 1) * 16);
    ldsm4(bh, bO);
    ldsm4(bl, bO + 2048);
    const uint32_t aO = sb + HT_OFF +
        (uint32_t)((warp_m*64 + (lane & 15)) * 32 + (lane >> 4) * 16);

    const int ecol = j*64 + warp_n*16 + (lane & 3) * 2;
    const float2 bg0 = *(const float2*)(bg + ecol);
    const float2 bg1 = *(const float2*)(bg + ecol + 8);
    const float2 bd0 = *(const float2*)(bD + ecol);
    const float2 bd1 = *(const float2*)(bD + ecol + 8);

    #pragma unroll
    for (int mi = 0; mi < 4; mi++) {
        uint32_t ah[4], al[4];
        ldsm4(ah, aO + mi * 512);
        ldsm4(al, aO + 4096 + mi * 512);
        float ya[2][4] = {};
        #pragma unroll
        for (int nj = 0; nj < 2; nj++) {
            mma16816(ya[nj], ah, &bh[nj*2]);
            mma16816(ya[nj], ah, &bl[nj*2]);
            mma16816(ya[nj], al, &bh[nj*2]);
        }
        #pragma unroll
        for (int nj = 0; nj < 2; nj++) {
            float2 bgv = nj ? bg1 : bg0;
            float2 bdv = nj ? bd1 : bd0;
            #pragma unroll
            for (int hl = 0; hl < 2; hl++) {
                int row = m0 + warp_m*64 + mi*16 + (lane >> 2) + hl*8;
                float g0 = 1.0f / (1.0f + __expf(-(d[mi][2*nj][hl*2+0] + bgv.x)));
                float g1 = 1.0f / (1.0f + __expf(-(d[mi][2*nj][hl*2+1] + bgv.y)));
                float x0 = d[mi][2*nj+1][hl*2+0] + bdv.x;
                float x1 = d[mi][2*nj+1][hl*2+1] + bdv.y;
                float2 o;
                o.x = ya[nj][hl*2+0] * g0 + x0 * (1.0f - g0);
                o.y = ya[nj][hl*2+1] * g1 + x1 * (1.0f - g1);
                *(float2*)(out + (size_t)row * DD + ecol + nj*8) = o;
            }
        }
    }
}

// ---------------------------------------------------------------------------
extern "C" void kernel_launch(void* const* d_in, const int* in_sizes, int n_in,
                              void* d_out, int out_size)
{
    const float* x  = (const float*)d_in[0];
    const float* WA = (const float*)d_in[1];
    const float* WB = (const float*)d_in[2];
    const float* WC = (const float*)d_in[3];
    const float* WD = (const float*)d_in[4];
    const float* bD = (const float*)d_in[5];
    const float* Wg = (const float*)d_in[6];
    const float* bg = (const float*)d_in[7];
    float* out = (float*)d_out;

    static cudaStream_t s2 = nullptr;
    static cudaEvent_t evA = nullptr, evB = nullptr;
    if (s2 == nullptr) {
        cudaStreamCreateWithFlags(&s2, cudaStreamNonBlocking);
        cudaEventCreateWithFlags(&evA, cudaEventDisableTiming);
        cudaEventCreateWithFlags(&evB, cudaEventDisableTiming);
        cudaFuncSetAttribute(main_kernel,
                             cudaFuncAttributeMaxDynamicSharedMemorySize, SMEM_BYTES);
        cudaFuncSetAttribute(prep_kernel,
                             cudaFuncAttributeMaxDynamicSharedMemorySize, PREP_SMEM);
    }

    // Fork: wmain (g_whi conversion) on side stream; hidden under prep+scanf.
    cudaEventRecord(evA, 0);
    cudaStreamWaitEvent(s2, evA, 0);
    wmain_kernel<<<2048, 256, 0, s2>>>(Wg, WD);
    cudaEventRecord(evB, s2);

    // Main-stream chain: wab -> prep -> scanf -> (join) -> main
    wab_kernel<<<192, 256>>>(WA, WB, WC);
    prep_kernel<<<256, 256, PREP_SMEM>>>(x);
    scanf_kernel<<<16, 512>>>();
    cudaStreamWaitEvent(0, evB, 0);
    main_kernel<<<dim3(16, 256), 256, SMEM_BYTES>>>(bD, bg, out);
}

// round 16
// speedup vs baseline: 1.0263x; 1.0263x over previous
#include <cuda_runtime.h>
#include <cuda_fp16.h>
#include <math.h>
#include <stdint.h>

#define BB 16
#define SS 2048
#define DD 1024
#define NN 16
#define M_TOT (BB*SS)   // 32768 tokens

// ---------------- scratch (__device__ globals) ------------------------------
__device__ __align__(256) float g_a[M_TOT*NN];
__device__ __align__(256) float g_b[M_TOT*NN];
__device__ __align__(256) __half g_hhi[M_TOT*NN];
__device__ __align__(256) __half g_hlo[M_TOT*NN];
__device__ __align__(256) __half g_xhi[(size_t)M_TOT*DD];
__device__ __align__(256) __half g_whi[2048*DD];
__device__ __align__(256) __half g_wabhi[32*DD];
__device__ __align__(256) __half g_wablo[32*DD];
__device__ __align__(256) __half g_wchi[DD*NN];
__device__ __align__(256) __half g_wclo[DD*NN];

// ---------------- PTX helpers ----------------------------------------------
__device__ __forceinline__ uint32_t smem_u32(const void* p) {
    uint32_t a;
    asm("{ .reg .u64 t; cvta.to.shared.u64 t, %1; cvt.u32.u64 %0, t; }" : "=r"(a) : "l"(p));
    return a;
}
__device__ __forceinline__ void cp16(uint32_t dst, const void* src) {
    asm volatile("cp.async.cg.shared.global [%0], [%1], 16;" :: "r"(dst), "l"(src) : "memory");
}
#define CP_COMMIT() asm volatile("cp.async.commit_group;" ::: "memory")
#define CP_WAIT1()  asm volatile("cp.async.wait_group 1;" ::: "memory")
#define CP_WAIT0()  asm volatile("cp.async.wait_group 0;" ::: "memory")

__device__ __forceinline__ void ldsm4(uint32_t* r, uint32_t addr) {
    asm volatile("ldmatrix.sync.aligned.m8n8.x4.shared.b16 {%0,%1,%2,%3}, [%4];"
                 : "=r"(r[0]), "=r"(r[1]), "=r"(r[2]), "=r"(r[3]) : "r"(addr));
}
__device__ __forceinline__ void mma16816(float* d, const uint32_t* a, const uint32_t* b) {
    asm volatile("mma.sync.aligned.m16n8k16.row.col.f32.f16.f16.f32 "
                 "{%0,%1,%2,%3}, {%4,%5,%6,%7}, {%8,%9}, {%0,%1,%2,%3};"
                 : "+f"(d[0]), "+f"(d[1]), "+f"(d[2]), "+f"(d[3])
                 : "r"(a[0]), "r"(a[1]), "r"(a[2]), "r"(a[3]), "r"(b[0]), "r"(b[1]));
}

// ---------------------------------------------------------------------------
// wfuse: blocks < 2048: W pair-interleave -> g_whi; blocks >= 2048: WA/WB/WC
// ---------------------------------------------------------------------------
__global__ __launch_bounds__(256) void wfuse_kernel(const float* __restrict__ Wg,
                                                    const float* __restrict__ WD,
                                                    const float* __restrict__ WA,
                                                    const float* __restrict__ WB,
                                                    const float* __restrict__ WC)
{
    int bx = blockIdx.x;
    if (bx < 2048) {
        int idx = bx * 256 + threadIdx.x;
        int r  = idx >> 8;
        int c4 = idx & 255;
        int j = r >> 8, q = r & 255;
        int p = q >> 4, s = q & 15;
        int e = j*128 + p*8 + (s & 7);
        const float* src = (s < 8) ? (Wg + (size_t)e * DD) : (WD + (size_t)e * DD);
        float4 v = ((const float4*)src)[c4];
        __half2 hA = __floats2half2_rn(v.x, v.y);
        __half2 hB = __floats2half2_rn(v.z, v.w);
        uint2 hp;
        hp.x = *(uint32_t*)&hA; hp.y = *(uint32_t*)&hB;
        *(uint2*)(g_whi + (size_t)r * DD + c4 * 4) = hp;
    } else {
        int id = (bx - 2048) * 256 + threadIdx.x;   // 192 blocks -> 49152
        float v;
        if (id < 32768) {
            int r = id >> 10, c = id & 1023;
            v = (r < 16) ? WA[(size_t)r * DD + c] : WB[(size_t)(r - 16) * DD + c];
            __half h = __float2half_rn(v);
            g_wabhi[id] = h;
            g_wablo[id] = __float2half_rn(v - __half2float(h));
        } else {
            int i2 = id - 32768;
            v = WC[i2];
            __half h = __float2half_rn(v);
            g_wchi[i2] = h;
            g_wclo[i2] = __float2half_rn(v - __half2float(h));
        }
    }
}

// ---------------------------------------------------------------------------
// prep: W resident in smem, double-buffered x staging, overlapped cp.async.
// a=tanh(x@WA^T), b=x@WB^T via 3-term fp16 HMMA; writes g_xhi.
// ---------------------------------------------------------------------------
#define PXF0 0
#define PXF1 32768
#define PXH  65536
#define PXL  81920
#define PWH  98304
#define PWL  163840
#define PREP_SMEM 229376
#define PXFS 256

__global__ __launch_bounds__(256) void prep_kernel(const float* __restrict__ x)
{
    extern __shared__ char smem[];
    uint32_t sb = smem_u32(smem);
    const int tid  = threadIdx.x;
    const int lane = tid & 31;
    const int wid  = tid >> 5;
    const int m0   = blockIdx.x * 128;
    const uint32_t lh = lane & 7;

    // W resident: 16 chunk-tiles (32 rows x 64 cols each), hi + lo
    #pragma unroll
    for (int i = 0; i < 16; i++) {
        int u = tid + i * 256;            // 0..4095
        int c = u >> 8, v = u & 255, row = v >> 3, c16 = v & 7;
        uint32_t off = (uint32_t)(c * 4096 + row * 128 + ((c16 ^ (row & 7)) << 4));
        const size_t gs = (size_t)row * DD + c * 64 + c16 * 8;
        cp16(sb + PWH + off, g_wabhi + gs);
        cp16(sb + PWL + off, g_wablo + gs);
    }
    CP_COMMIT();
    // x chunk 0
    #pragma unroll
    for (int i = 0; i < 8; i++) {
        int u = tid + i * 256;
        int row = u >> 4, q = u & 15;
        cp16(sb + PXF0 + row * PXFS + q * 16, x + (size_t)(m0 + row) * DD + q * 4);
    }
    CP_COMMIT();

    float acc[4][4] = {};

    for (int kc = 0; kc < 16; kc++) {
        CP_WAIT0();                        // x chunk kc (+ W at kc=0)
        if (kc < 15) {
            uint32_t nbuf = ((kc + 1) & 1) ? PXF1 : PXF0;
            #pragma unroll
            for (int i = 0; i < 8; i++) {
                int u = tid + i * 256;
                int row = u >> 4, q = u & 15;
                cp16(sb + nbuf + row * PXFS + q * 16,
                     x + (size_t)(m0 + row) * DD + (kc + 1) * 64 + q * 4);
            }
            CP_COMMIT();
        }
        uint32_t pxf = (kc & 1) ? PXF1 : PXF0;
        #pragma unroll
        for (int i = 0; i < 8; i++) {
            int u = tid + i * 256;
            int row = u >> 4, q = u & 15;
            float4 v = *(const float4*)(smem + pxf + row * PXFS + q * 16);
            __half hx = __float2half_rn(v.x), hy = __float2half_rn(v.y);
            __half hz = __float2half_rn(v.z), hw = __float2half_rn(v.w);
            __half2 hA = __halves2half2(hx, hy), hB = __halves2half2(hz, hw);
            __half2 lA = __floats2half2_rn(v.x - __half2float(hx), v.y - __half2float(hy));
            __half2 lB = __floats2half2_rn(v.z - __half2float(hz), v.w - __half2float(hw));
            uint2 hp, lp;
            hp.x = *(uint32_t*)&hA; hp.y = *(uint32_t*)&hB;
            lp.x = *(uint32_t*)&lA; lp.y = *(uint32_t*)&lB;
            int c16 = q >> 1;
            uint32_t soff = row * 128 + (((uint32_t)c16 ^ (row & 7)) << 4) + (q & 1) * 8;
            *(uint2*)(smem + PXH + soff) = hp;
            *(uint2*)(smem + PXL + soff) = lp;
            *(uint2*)(g_xhi + (size_t)(m0 + row) * DD + kc * 64 + q * 4) = hp;
        }
        __syncthreads();

        const uint32_t aBase = (uint32_t)((wid * 16 + (lane & 15)) * 128);
        const uint32_t bRow  = (uint32_t)(((lane >> 4) << 3) + lh);
        const uint32_t wchk  = (uint32_t)(kc * 4096);
        #pragma unroll
        for (int kk = 0; kk < 4; kk++) {
            uint32_t aSw = (((uint32_t)(kk*2) + (lane >> 4)) ^ lh) << 4;
            uint32_t bSw = (((uint32_t)(kk*2) + ((lane >> 3) & 1)) ^ lh) << 4;
            uint32_t ah[4], al[4], bh[8], bl[8];
            ldsm4(ah, sb + PXH + aBase + aSw);
            ldsm4(al, sb + PXL + aBase + aSw);
            ldsm4(&bh[0], sb + PWH + wchk + bRow * 128 + bSw);
            ldsm4(&bh[4], sb + PWH + wchk + (bRow + 16) * 128 + bSw);
            ldsm4(&bl[0], sb + PWL + wchk + bRow * 128 + bSw);
            ldsm4(&bl[4], sb + PWL + wchk + (bRow + 16) * 128 + bSw);
            #pragma unroll
            for (int ni = 0; ni < 4; ni++) {
                mma16816(acc[ni], ah, &bh[ni*2]);
                mma16816(acc[ni], ah, &bl[ni*2]);
                mma16816(acc[ni], al, &bh[ni*2]);
            }
        }
        __syncthreads();
    }

    #pragma unroll
    for (int ni = 0; ni < 4; ni++) {
        #pragma unroll
        for (int fr = 0; fr < 4; fr++) {
            int row = m0 + wid*16 + (lane >> 2) + (fr >> 1) * 8;
            int col = ni*8 + (lane & 3) * 2 + (fr & 1);
            float v = acc[ni][fr];
            if (col < 16) g_a[(size_t)row * NN + col]        = tanhf(v);
            else          g_b[(size_t)row * NN + (col - 16)] = v;
        }
    }
}

// ---------------------------------------------------------------------------
// Fused scan v2: grid 16, 1024 thr = 16 chains x 64 chunks of 32 steps.
// Phase1 per-thread chunk scan; Phase2 16-thread serial prefix (64 steps);
// Phase3 rescan with carry, emit fp16 hi/lo.
// ---------------------------------------------------------------------------
__global__ __launch_bounds__(1024) void scanf_kernel()
{
    __shared__ float sA[16*65];
    __shared__ float sB[16*65];
    const int tid = threadIdx.x;
    const int n  = tid & 15;
    const int ch = tid >> 4;          // 0..63
    const int b  = blockIdx.x;
    const size_t base = ((size_t)b * SS + ch * 32) * NN + n;

    float A = 1.0f, h = 0.0f;
    #pragma unroll 4
    for (int i = 0; i < 32; i++) {
        float av = g_a[base + (size_t)i * NN];
        float bv = g_b[base + (size_t)i * NN];
        A *= av;
        h = fmaf(av, h, bv);
    }
    sA[n*65 + ch] = A;
    sB[n*65 + ch] = h;
    __syncthreads();

    if (tid < 16) {
        float carry = 0.0f;
        #pragma unroll
        for (int c = 0; c < 64; c++) {
            float a2 = sA[tid*65 + c];
            float b2 = sB[tid*65 + c];
            sB[tid*65 + c] = carry;
            carry = fmaf(a2, carry, b2);
        }
    }
    __syncthreads();

    h = sB[n*65 + ch];
    #pragma unroll 4
    for (int i = 0; i < 32; i++) {
        size_t idx = base + (size_t)i * NN;
        h = fmaf(g_a[idx], h, g_b[idx]);
        __half hh = __float2half_rn(h);
        g_hhi[idx] = hh;
        g_hlo[idx] = __float2half_rn(h - __half2float(hh));
    }
}

// ---------------------------------------------------------------------------
// Main: CTA 128x128, 256 thr, grid (16, 256), 2 CTAs/SM. Single-term fp16,
// 3-stage ring (prologue {0,1}; wait1 -> sync -> prefetch c+2 -> compute c),
// register epilogue (y-GEMM + gating).
// ---------------------------------------------------------------------------
#define STG      32768               // A 16K | W 16K
#define SW       16384
#define HT_OFF   (3*STG)             // 98304: hhi(4K)|hlo(4K)|wchi(2K)|wclo(2K)
#define SMEM_BYTES (HT_OFF + 12288)  // 110592 -> 2 CTAs/SM
#define NCH 16

__device__ __forceinline__ void load_chunk(uint32_t sb, int c, int m0, int jw, int tid)
{
    int kc = c * 64;
    uint32_t buf = sb + (uint32_t)(c % 3) * STG;
    #pragma unroll
    for (int i = 0; i < 8; i++) {
        int u = tid + i * 256;        // 2048 cp16
        if (u < 1024) {               // A: 128 rows x 8 c16
            int row = u >> 3, c16 = u & 7;
            cp16(buf + row * 128 + ((c16 ^ (row & 7)) << 4),
                 g_xhi + (size_t)(m0 + row) * DD + kc + c16 * 8);
        } else {                      // W: 128 rows x 8 c16
            int v = u - 1024;
            int row = v >> 3, c16 = v & 7;
            cp16(buf + SW + row * 128 + ((c16 ^ (row & 7)) << 4),
                 g_whi + (size_t)(jw + row) * DD + kc + c16 * 8);
        }
    }
    CP_COMMIT();
}

__global__ __launch_bounds__(256, 2) void main_kernel(const float* __restrict__ bD,
                                                      const float* __restrict__ bg,
                                                      float* __restrict__ out)
{
    extern __shared__ char smem[];
    uint32_t sb = smem_u32(smem);
    const int tid    = threadIdx.x;
    const int lane   = tid & 31;
    const int wid    = tid >> 5;
    const int warp_m = wid & 1;       // 2 m-groups of 64 rows
    const int warp_n = wid >> 1;      // 4 n-groups of 32 cols
    const int j  = blockIdx.x;        // 0..15
    const int m0 = blockIdx.y * 128;
    const int jw = j * 128;
    const uint32_t lh = lane & 7;

    // HT tiles: hhi|hlo (128x16) + wchi|wclo (64x16) -> 768 cp16
    #pragma unroll
    for (int i = 0; i < 3; i++) {
        int u = tid + i * 256;            // 0..767
        const __half* src;
        uint32_t dst;
        if (u < 512) {                    // hhi / hlo
            int region = u >> 8, v = u & 255;
            int row = v >> 1, c16 = v & 1;
            src = (region == 0 ? g_hhi : g_hlo) + (size_t)(m0 + row) * NN + c16 * 8;
            dst = sb + HT_OFF + region * 4096 + row * 32 + c16 * 16;
        } else {                          // wchi / wclo
            int v = u - 512;
            int region = v >> 7, w = v & 127;
            int row = w >> 1, c16 = w & 1;
            src = (region == 0 ? g_wchi : g_wclo) + (size_t)(j*64 + row) * NN + c16 * 8;
            dst = sb + HT_OFF + 8192 + region * 2048 + row * 32 + c16 * 16;
        }
        cp16(dst, src);
    }
    load_chunk(sb, 0, m0, jw, tid);   // group 0 (includes HT)
    load_chunk(sb, 1, m0, jw, tid);   // group 1

    float d[4][4][4] = {};

    const uint32_t aBase = (uint32_t)((warp_m*64 + (lane & 15)) * 128);
    const uint32_t aHalf = (uint32_t)(lane >> 4);
    const uint32_t bBase = (uint32_t)(SW + (warp_n*32 + ((lane >> 4) << 3) + lh) * 128);
    const uint32_t bHalf = (uint32_t)((lane >> 3) & 1);

    for (int c = 0; c < NCH; c++) {
        if (c + 1 == NCH) CP_WAIT0(); else CP_WAIT1();
        __syncthreads();
        if (c + 2 < NCH) load_chunk(sb, c + 2, m0, jw, tid);

        uint32_t buf = sb + (uint32_t)(c % 3) * STG;
        #pragma unroll
        for (int kk = 0; kk < 4; kk++) {
            uint32_t aSw = (((uint32_t)(kk*2) + aHalf) ^ lh) << 4;
            uint32_t bSw = (((uint32_t)(kk*2) + bHalf) ^ lh) << 4;
            uint32_t b[8], a[4][4];
            ldsm4(&b[0], buf + bBase + bSw);
            ldsm4(&b[4], buf + bBase + 2048 + bSw);
            #pragma unroll
            for (int mi = 0; mi < 4; mi++)
                ldsm4(a[mi], buf + aBase + mi * 2048 + aSw);
            #pragma unroll
            for (int mi = 0; mi < 4; mi++)
                #pragma unroll
                for (int ni = 0; ni < 4; ni++)
                    mma16816(d[mi][ni], a[mi], &b[ni*2]);
        }
    }

    // ---- register epilogue: y = hs@WC^T (3-term fp16), then gating ----
    uint32_t bh[4], bl[4];
    const uint32_t bO = sb + HT_OFF + 8192 +
        (uint32_t)((warp_n*16 + ((lane >> 4) << 3) + lh) * 32 + ((lane >> 3) & 1) * 16);
    ldsm4(bh, bO);
    ldsm4(bl, bO + 2048);
    const uint32_t aO = sb + HT_OFF +
        (uint32_t)((warp_m*64 + (lane & 15)) * 32 + (lane >> 4) * 16);

    const int ecol = j*64 + warp_n*16 + (lane & 3) * 2;
    const float2 bg0 = *(const float2*)(bg + ecol);
    const float2 bg1 = *(const float2*)(bg + ecol + 8);
    const float2 bd0 = *(const float2*)(bD + ecol);
    const float2 bd1 = *(const float2*)(bD + ecol + 8);

    #pragma unroll
    for (int mi = 0; mi < 4; mi++) {
        uint32_t ah[4], al[4];
        ldsm4(ah, aO + mi * 512);
        ldsm4(al, aO + 4096 + mi * 512);
        float ya[2][4] = {};
        #pragma unroll
        for (int nj = 0; nj < 2; nj++) {
            mma16816(ya[nj], ah, &bh[nj*2]);
            mma16816(ya[nj], ah, &bl[nj*2]);
            mma16816(ya[nj], al, &bh[nj*2]);
        }
        #pragma unroll
        for (int nj = 0; nj < 2; nj++) {
            float2 bgv = nj ? bg1 : bg0;
            float2 bdv = nj ? bd1 : bd0;
            #pragma unroll
            for (int hl = 0; hl < 2; hl++) {
                int row = m0 + warp_m*64 + mi*16 + (lane >> 2) + hl*8;
                float g0 = 1.0f / (1.0f + __expf(-(d[mi][2*nj][hl*2+0] + bgv.x)));
                float g1 = 1.0f / (1.0f + __expf(-(d[mi][2*nj][hl*2+1] + bgv.y)));
                float x0 = d[mi][2*nj+1][hl*2+0] + bdv.x;
                float x1 = d[mi][2*nj+1][hl*2+1] + bdv.y;
                float2 o;
                o.x = ya[nj][hl*2+0] * g0 + x0 * (1.0f - g0);
                o.y = ya[nj][hl*2+1] * g1 + x1 * (1.0f - g1);
                *(float2*)(out + (size_t)row * DD + ecol + nj*8) = o;
            }
        }
    }
}

// ---------------------------------------------------------------------------
extern "C" void kernel_launch(void* const* d_in, const int* in_sizes, int n_in,
                              void* d_out, int out_size)
{
    const float* x  = (const float*)d_in[0];
    const float* WA = (const float*)d_in[1];
    const float* WB = (const float*)d_in[2];
    const float* WC = (const float*)d_in[3];
    const float* WD = (const float*)d_in[4];
    const float* bD = (const float*)d_in[5];
    const float* Wg = (const float*)d_in[6];
    const float* bg = (const float*)d_in[7];
    float* out = (float*)d_out;

    cudaFuncSetAttribute(main_kernel,
                         cudaFuncAttributeMaxDynamicSharedMemorySize, SMEM_BYTES);
    cudaFuncSetAttribute(prep_kernel,
                         cudaFuncAttributeMaxDynamicSharedMemorySize, PREP_SMEM);

    wfuse_kernel<<<2240, 256>>>(Wg, WD, WA, WB, WC);
    prep_kernel<<<256, 256, PREP_SMEM>>>(x);
    scanf_kernel<<<16, 1024>>>();
    main_kernel<<<dim3(16, 256), 256, SMEM_BYTES>>>(bD, bg, out);
}